// round 8
// baseline (speedup 1.0000x reference)
#include <cuda_runtime.h>
#include <cstdint>

// Problem constants
#define NROWS 65536
#define DDIM  64
#define KEMB  8192

#define BM 128
#define BN 128
#define NTILES (KEMB / BN)      // 64
#define NTHREADS 512            // 16 warps: 8 row-groups x 2 col-groups

// Output layout (flattened fp32): quantized | vq_loss | commit_loss | idx
#define OUT_LOSS   (NROWS * DDIM)
#define OUT_IDX    (NROWS * DDIM + 2)
#define NPARTIAL   1024

// smem byte offsets
#define SM_B0    0               // 32768: [n][kw] interleaved (hi,lo) bf16x2 pairs
#define SM_B1    32768           // 32768
#define SM_ESALL 65536           // 32768: all 8192 e_sq values
#define SM_Z     98304           // 34816: 128 x 68 f32 (padded)
#define SM_ZSQ   133120          // 512
#define SM_RV    133632          // 512
#define SM_RI    134144          // 512
#define SMEM_TOTAL 134656

// scratch
__device__ float g_esq[KEMB];
__device__ int   g_idx[NROWS];
__device__ float g_partial[NPARTIAL];

// ---------------------------------------------------------------------------
__device__ __forceinline__ uint32_t pack_bf16x2(float lo, float hi) {
    uint32_t d;
    asm("cvt.rn.bf16x2.f32 %0, %1, %2;" : "=r"(d) : "f"(hi), "f"(lo));
    return d;
}
__device__ __forceinline__ float bf_lo(uint32_t u) { return __uint_as_float(u << 16); }
__device__ __forceinline__ float bf_hi(uint32_t u) { return __uint_as_float(u & 0xffff0000u); }

// split a float pair into bf16x2 hi + bf16x2 lo(residual)
__device__ __forceinline__ void split_pair(float f0, float f1,
                                           uint32_t& h, uint32_t& l) {
    h = pack_bf16x2(f0, f1);
    l = pack_bf16x2(f0 - bf_lo(h), f1 - bf_hi(h));
}

__device__ __forceinline__ void mma16(float c[4], const uint32_t a[4],
                                      uint32_t b0, uint32_t b1) {
    asm volatile(
        "mma.sync.aligned.m16n8k16.row.col.f32.bf16.bf16.f32 "
        "{%0,%1,%2,%3},{%4,%5,%6,%7},{%8,%9},{%0,%1,%2,%3};"
        : "+f"(c[0]), "+f"(c[1]), "+f"(c[2]), "+f"(c[3])
        : "r"(a[0]), "r"(a[1]), "r"(a[2]), "r"(a[3]), "r"(b0), "r"(b1));
}
__device__ __forceinline__ uint32_t smem_u32(const void* p) {
    uint32_t a;
    asm("{ .reg .u64 t; cvta.to.shared.u64 t, %1; cvt.u32.u64 %0, t; }"
        : "=r"(a) : "l"(p));
    return a;
}
__device__ __forceinline__ void cp16(uint32_t dst, const void* src) {
    asm volatile("cp.async.cg.shared.global [%0], [%1], 16;"
                 :: "r"(dst), "l"(src) : "memory");
}
#define CP_COMMIT() asm volatile("cp.async.commit_group;" ::: "memory")
#define CP_WAIT0()  asm volatile("cp.async.wait_group 0;" ::: "memory")

// ---------------------------------------------------------------------------
// Kernel 1: e_sq (sequential fp32 chain)
// ---------------------------------------------------------------------------
__global__ void esq_kernel(const float* __restrict__ E) {
    int k = blockIdx.x * blockDim.x + threadIdx.x;
    if (k < KEMB) {
        const float* row = E + k * DDIM;
        float s = 0.f;
#pragma unroll
        for (int d = 0; d < DDIM; d++) s = fmaf(row[d], row[d], s);
        g_esq[k] = s;
    }
}

// ---------------------------------------------------------------------------
// B tile staging: split 16 f32 (one quarter-row) into 8 (hi,lo) word pairs.
// Layout: byte = n*256 + ((kw ^ ((n&7)<<2)) << 3), pair = {hi_bf16x2, lo_bf16x2}
// ---------------------------------------------------------------------------
__device__ __forceinline__ void stage_b_sts(const float4 pf[4], char* dst, int tid)
{
    const int n   = tid >> 2;
    const int kw0 = (tid & 3) * 8;
    const int sw  = (n & 7) << 2;
    uint32_t h[8], l[8];
    split_pair(pf[0].x, pf[0].y, h[0], l[0]);
    split_pair(pf[0].z, pf[0].w, h[1], l[1]);
    split_pair(pf[1].x, pf[1].y, h[2], l[2]);
    split_pair(pf[1].z, pf[1].w, h[3], l[3]);
    split_pair(pf[2].x, pf[2].y, h[4], l[4]);
    split_pair(pf[2].z, pf[2].w, h[5], l[5]);
    split_pair(pf[3].x, pf[3].y, h[6], l[6]);
    split_pair(pf[3].z, pf[3].w, h[7], l[7]);
    char* row = dst + n * 256;
#pragma unroll
    for (int w = 0; w < 8; w++) {
        int kw = kw0 + w;
        unsigned long long v =
            (unsigned long long)h[w] | ((unsigned long long)l[w] << 32);
        *reinterpret_cast<unsigned long long*>(row + ((kw ^ sw) << 3)) = v;
    }
}

// ---------------------------------------------------------------------------
// Kernel 2: bf16 3-term split argmin GEMM, 16 warps, pre-split B in smem
// ---------------------------------------------------------------------------
__global__ __launch_bounds__(NTHREADS, 1) void vq_mma_kernel(
    const float* __restrict__ Z, const float* __restrict__ E)
{
    extern __shared__ __align__(16) char sm[];
    float* Zs    = reinterpret_cast<float*>(sm + SM_Z);
    float* ESALL = reinterpret_cast<float*>(sm + SM_ESALL);
    float* ZSQ   = reinterpret_cast<float*>(sm + SM_ZSQ);
    float* RV    = reinterpret_cast<float*>(sm + SM_RV);
    int*   RI    = reinterpret_cast<int*>(sm + SM_RI);
    const uint32_t smb = smem_u32(sm);

    const int tid  = threadIdx.x;
    const int lane = tid & 31;
    const int warp = tid >> 5;
    const int cg   = warp & 1;          // col group (0/1) -> 64 cols
    const int rw   = warp >> 1;         // row group (0..7) -> 16 rows
    const int g    = lane >> 2;         // 0..7
    const int tq   = lane & 3;          // 0..3
    const int rowBase = blockIdx.x * BM;

    // ---- e_sq table: whole thing into smem via cp.async (once) ----
#pragma unroll
    for (int i = 0; i < 4; i++) {
        int c = tid + i * 512;          // 0..2047 float4 chunks
        cp16(smb + SM_ESALL + c * 16, g_esq + c * 4);
    }
    CP_COMMIT();

    // ---- B tile 0: LDG -> split -> STS ----
    float4 pf[4];
    {
        const float4* sp = reinterpret_cast<const float4*>(
            E + (size_t)(tid >> 2) * DDIM + (tid & 3) * 16);
#pragma unroll
        for (int q = 0; q < 4; q++) pf[q] = sp[q];
        stage_b_sts(pf, sm + SM_B0, tid);
    }
    // ---- prefetch B tile 1 into regs ----
    {
        const float4* sp = reinterpret_cast<const float4*>(
            E + (size_t)(BN + (tid >> 2)) * DDIM + (tid & 3) * 16);
#pragma unroll
        for (int q = 0; q < 4; q++) pf[q] = sp[q];
    }

    // ---- stage Z tile (plain fp32, pad-68 rows) ----
    {
        const float4* zp = reinterpret_cast<const float4*>(Z + (size_t)rowBase * DDIM);
#pragma unroll
        for (int i = 0; i < 4; i++) {
            int c = tid + i * 512;
            int m = c >> 4, kc = c & 15;
            float4 v = zp[c];
            *reinterpret_cast<float4*>(&Zs[m * 68 + kc * 4]) = v;
        }
    }
    __syncthreads();

    // ---- zsq: exact sequential fp32 chain ----
    if (tid < BM) {
        float s = 0.f;
#pragma unroll
        for (int d = 0; d < DDIM; d++) {
            float v = Zs[tid * 68 + d];
            s = fmaf(v, v, s);
        }
        ZSQ[tid] = s;
    }

    // ---- build A fragments (bf16 hi + lo residual), registers ----
    uint32_t ah[4][4], al[4][4];
    {
        const int r0 = rw * 16 + g;
#pragma unroll
        for (int kc = 0; kc < 4; kc++) {
            const int k0 = kc * 16 + 2 * tq;
            float2 p0 = *reinterpret_cast<const float2*>(&Zs[r0 * 68 + k0]);
            float2 p1 = *reinterpret_cast<const float2*>(&Zs[(r0 + 8) * 68 + k0]);
            float2 p2 = *reinterpret_cast<const float2*>(&Zs[r0 * 68 + k0 + 8]);
            float2 p3 = *reinterpret_cast<const float2*>(&Zs[(r0 + 8) * 68 + k0 + 8]);
            split_pair(p0.x, p0.y, ah[kc][0], al[kc][0]);
            split_pair(p1.x, p1.y, ah[kc][1], al[kc][1]);
            split_pair(p2.x, p2.y, ah[kc][2], al[kc][2]);
            split_pair(p3.x, p3.y, ah[kc][3], al[kc][3]);
        }
    }
    CP_WAIT0();
    __syncthreads();    // ZSQ + B0 + ESALL visible

    float zsqv[2];
    zsqv[0] = ZSQ[rw * 16 + g];
    zsqv[1] = ZSQ[rw * 16 + 8 + g];

    float bv[2] = {3.4e38f, 3.4e38f};
    int   bi[2] = {0, 0};

    const int swg = g << 2;

    for (int t = 0; t < NTILES; t++) {
        if (t) __syncthreads();   // prior tile's readers done; STS target free

        // stage tile t+1 from regs, prefetch tile t+2
        if (t + 1 < NTILES)
            stage_b_sts(pf, sm + (((t + 1) & 1) ? SM_B1 : SM_B0), tid);
        if (t + 2 < NTILES) {
            const float4* sp = reinterpret_cast<const float4*>(
                E + (size_t)((t + 2) * BN + (tid >> 2)) * DDIM + (tid & 3) * 16);
#pragma unroll
            for (int q = 0; q < 4; q++) pf[q] = sp[q];
        }
        __syncthreads();          // B[t&1] fully visible (written iter t-1)

        const char* Bbuf = sm + ((t & 1) ? SM_B1 : SM_B0);

        float acc[8][4];
#pragma unroll
        for (int nf = 0; nf < 8; nf++)
#pragma unroll
            for (int j = 0; j < 4; j++) acc[nf][j] = 0.f;

#pragma unroll
        for (int nf = 0; nf < 8; nf++) {
            const char* rowp = Bbuf + (cg * 64 + nf * 8 + g) * 256;
#pragma unroll
            for (int kc = 0; kc < 4; kc++) {
                const int ki0 = ((kc * 8 + tq) ^ swg) << 3;
                uint2 v0 = *reinterpret_cast<const uint2*>(rowp + ki0);
                uint2 v1 = *reinterpret_cast<const uint2*>(rowp + (ki0 ^ 32));
                mma16(acc[nf], ah[kc], v0.x, v1.x);   // hh
                mma16(acc[nf], ah[kc], v0.y, v1.y);   // hl
                mma16(acc[nf], al[kc], v0.x, v1.x);   // lh
            }
        }

        // ---- epilogue: d2 = fl(fl(zsq - 2 dot) + es), running min ----
        const float* EST = ESALL + t * 128;
        const int colT = t * BN + cg * 64;
#pragma unroll
        for (int nf = 0; nf < 8; nf++) {
            float2 ep2 = *reinterpret_cast<const float2*>(
                &EST[cg * 64 + nf * 8 + 2 * tq]);
#pragma unroll
            for (int j = 0; j < 4; j++) {
                float es = (j & 1) ? ep2.y : ep2.x;
                int ri = j >> 1;
                float tt = fmaf(-2.0f, acc[nf][j], zsqv[ri]);
                float d2 = tt + es;
                int col = colT + nf * 8 + 2 * tq + (j & 1);
                if (d2 < bv[ri]) { bv[ri] = d2; bi[ri] = col; }
            }
        }
    }

    // ---- reduce across the 4 tq lanes sharing each row (tie -> lowest col) ----
#pragma unroll
    for (int ri = 0; ri < 2; ri++) {
        float v = bv[ri];
        int   x = bi[ri];
#pragma unroll
        for (int off = 1; off <= 2; off <<= 1) {
            float ov = __shfl_xor_sync(0xFFFFFFFFu, v, off);
            int   ox = __shfl_xor_sync(0xFFFFFFFFu, x, off);
            if (ov < v || (ov == v && ox < x)) { v = ov; x = ox; }
        }
        bv[ri] = v; bi[ri] = x;
    }
    __syncthreads();
    if (tq == 0 && cg == 0) {
#pragma unroll
        for (int ri = 0; ri < 2; ri++) {
            int row = rw * 16 + ri * 8 + g;
            RV[row] = bv[ri]; RI[row] = bi[ri];
        }
    }
    __syncthreads();
    if (tq == 0 && cg == 1) {
#pragma unroll
        for (int ri = 0; ri < 2; ri++) {
            int row = rw * 16 + ri * 8 + g;
            float v0 = RV[row]; int i0 = RI[row];
            int win = (bv[ri] < v0 || (bv[ri] == v0 && bi[ri] < i0)) ? bi[ri] : i0;
            g_idx[rowBase + row] = win;
        }
    }
}

// ---------------------------------------------------------------------------
// Kernel 3: gather + partial loss + index-as-float
// ---------------------------------------------------------------------------
__global__ __launch_bounds__(256) void gather_loss_kernel(
    const float* __restrict__ Z, const float* __restrict__ E,
    float* __restrict__ out)
{
    __shared__ float red[256];
    const int tid  = threadIdx.x;
    const int gtid = blockIdx.x * blockDim.x + tid;

    float lsum = 0.f;
    const float4* Z4 = reinterpret_cast<const float4*>(Z);
    float4* O4 = reinterpret_cast<float4*>(out);

#pragma unroll
    for (int j = 0; j < 4; j++) {
        int f   = gtid * 4 + j;
        int row = f >> 4;
        int dc  = (f & 15);
        int idx = g_idx[row];
        const float4* E4 = reinterpret_cast<const float4*>(E + (size_t)idx * DDIM);
        float4 q = E4[dc];
        float4 z = Z4[f];
        O4[f] = q;
        float dx = z.x - q.x, dy = z.y - q.y, dz = z.z - q.z, dw = z.w - q.w;
        lsum += dx * dx + dy * dy + dz * dz + dw * dw;
    }

    if (gtid < NROWS) out[OUT_IDX + gtid] = (float)g_idx[gtid];

    red[tid] = lsum;
    __syncthreads();
    for (int s = 128; s > 0; s >>= 1) {
        if (tid < s) red[tid] += red[tid + s];
        __syncthreads();
    }
    if (tid == 0) g_partial[blockIdx.x] = red[0];
}

// ---------------------------------------------------------------------------
// Kernel 4: finalize losses
// ---------------------------------------------------------------------------
__global__ __launch_bounds__(512) void finalize_kernel(float* __restrict__ out) {
    __shared__ float red[512];
    int tid = threadIdx.x;
    red[tid] = g_partial[tid] + g_partial[tid + 512];
    __syncthreads();
    for (int s = 256; s > 0; s >>= 1) {
        if (tid < s) red[tid] += red[tid + s];
        __syncthreads();
    }
    if (tid == 0) {
        float loss = red[0] * (1.0f / (float)(NROWS * DDIM)); // N*D = 2^22, exact
        out[OUT_LOSS + 0] = loss;
        out[OUT_LOSS + 1] = loss;
    }
}

// ---------------------------------------------------------------------------
extern "C" void kernel_launch(void* const* d_in, const int* in_sizes, int n_in,
                              void* d_out, int out_size)
{
    const float* Z = (const float*)d_in[0];
    const float* E = (const float*)d_in[1];
    if (n_in >= 2 && in_sizes[0] == KEMB * DDIM && in_sizes[1] == NROWS * DDIM) {
        const float* t = Z; Z = E; E = t;
    }
    float* out = (float*)d_out;

    cudaFuncSetAttribute(vq_mma_kernel,
                         cudaFuncAttributeMaxDynamicSharedMemorySize, SMEM_TOTAL);

    esq_kernel<<<KEMB / 256, 256>>>(E);
    vq_mma_kernel<<<NROWS / BM, NTHREADS, SMEM_TOTAL>>>(Z, E);
    gather_loss_kernel<<<NPARTIAL, 256>>>(Z, E, out);
    finalize_kernel<<<1, 512>>>(out);
}

// round 9
// speedup vs baseline: 1.0345x; 1.0345x over previous
#include <cuda_runtime.h>
#include <cstdint>

// Problem constants
#define NROWS 65536
#define DDIM  64
#define KEMB  8192

#define BM 128
#define BN 128
#define NTILES (KEMB / BN)      // 64
#define NTHREADS 256            // 8 warps: 4 row-groups x 2 col-groups

// Output layout (flattened fp32): quantized | vq_loss | commit_loss | idx
#define OUT_LOSS   (NROWS * DDIM)
#define OUT_IDX    (NROWS * DDIM + 2)
#define NPARTIAL   1024

// smem byte offsets
#define SM_B0    0               // 32768: [n][kw] interleaved (hi,lo) bf16x2 pairs
#define SM_B1    32768
#define SM_B2    65536
#define SM_ESALL 98304           // 32768: all 8192 e_sq values
#define SM_Z     131072          // 34816: 128 x 68 f32 (padded)
#define SM_ZSQ   165888          // 512
#define SM_RV    166400          // 512
#define SM_RI    166912          // 512
#define SMEM_TOTAL 167424

typedef unsigned long long ull;

// scratch
__device__ float g_esq[KEMB];
__device__ int   g_idx[NROWS];
__device__ float g_partial[NPARTIAL];

// ---------------------------------------------------------------------------
__device__ __forceinline__ uint32_t pack_bf16x2(float lo, float hi) {
    uint32_t d;
    asm("cvt.rn.bf16x2.f32 %0, %1, %2;" : "=r"(d) : "f"(hi), "f"(lo));
    return d;
}
__device__ __forceinline__ float bf_lo(uint32_t u) { return __uint_as_float(u << 16); }
__device__ __forceinline__ float bf_hi(uint32_t u) { return __uint_as_float(u & 0xffff0000u); }

__device__ __forceinline__ void split_pair(float f0, float f1,
                                           uint32_t& h, uint32_t& l) {
    h = pack_bf16x2(f0, f1);
    l = pack_bf16x2(f0 - bf_lo(h), f1 - bf_hi(h));
}

__device__ __forceinline__ void mma16(float c[4], const uint32_t a[4],
                                      uint32_t b0, uint32_t b1) {
    asm volatile(
        "mma.sync.aligned.m16n8k16.row.col.f32.bf16.bf16.f32 "
        "{%0,%1,%2,%3},{%4,%5,%6,%7},{%8,%9},{%0,%1,%2,%3};"
        : "+f"(c[0]), "+f"(c[1]), "+f"(c[2]), "+f"(c[3])
        : "r"(a[0]), "r"(a[1]), "r"(a[2]), "r"(a[3]), "r"(b0), "r"(b1));
}
__device__ __forceinline__ uint32_t smem_u32(const void* p) {
    uint32_t a;
    asm("{ .reg .u64 t; cvta.to.shared.u64 t, %1; cvt.u32.u64 %0, t; }"
        : "=r"(a) : "l"(p));
    return a;
}
__device__ __forceinline__ void cp16(uint32_t dst, const void* src) {
    asm volatile("cp.async.cg.shared.global [%0], [%1], 16;"
                 :: "r"(dst), "l"(src) : "memory");
}
#define CP_COMMIT() asm volatile("cp.async.commit_group;" ::: "memory")
#define CP_WAIT0()  asm volatile("cp.async.wait_group 0;" ::: "memory")

// ---------------------------------------------------------------------------
// Kernel 1: e_sq (sequential fp32 chain)
// ---------------------------------------------------------------------------
__global__ void esq_kernel(const float* __restrict__ E) {
    int k = blockIdx.x * blockDim.x + threadIdx.x;
    if (k < KEMB) {
        const float* row = E + k * DDIM;
        float s = 0.f;
#pragma unroll
        for (int d = 0; d < DDIM; d++) s = fmaf(row[d], row[d], s);
        g_esq[k] = s;
    }
}

// ---------------------------------------------------------------------------
// Split 8 float4 (half a B row) into interleaved (hi,lo) bf16x2 pairs + STS.
// Thread mapping (256 threads): n = tid>>1 (row), half = tid&1 (k half).
// Layout per row (256 B): pair kw at byte ((kw ^ ((n&7)<<2)) << 3).
// ---------------------------------------------------------------------------
__device__ __forceinline__ void split_sts_half(const float4 pf[8], char* dst, int tid)
{
    const int n    = tid >> 1;
    const int half = tid & 1;
    const int sw   = (n & 7) << 2;
    const int kw0  = half * 16;
    char* row = dst + n * 256;
#pragma unroll
    for (int q = 0; q < 8; q++) {
        uint32_t h0, l0, h1, l1;
        split_pair(pf[q].x, pf[q].y, h0, l0);
        split_pair(pf[q].z, pf[q].w, h1, l1);
        int kw = kw0 + q * 2;
        *reinterpret_cast<ull*>(row + ((kw ^ sw) << 3)) =
            (ull)h0 | ((ull)l0 << 32);
        *reinterpret_cast<ull*>(row + (((kw + 1) ^ sw) << 3)) =
            (ull)h1 | ((ull)l1 << 32);
    }
}
__device__ __forceinline__ void ldg_half(float4 pf[8], const float* __restrict__ Etile,
                                         int tid)
{
    const int n    = tid >> 1;
    const int half = tid & 1;
    const float4* sp = reinterpret_cast<const float4*>(Etile + (size_t)n * DDIM) + half * 8;
#pragma unroll
    for (int q = 0; q < 8; q++) pf[q] = sp[q];
}

// ---------------------------------------------------------------------------
// Kernel 2: bf16 3-term split argmin GEMM, triple-buffered pre-split B
// ---------------------------------------------------------------------------
__global__ __launch_bounds__(NTHREADS, 1) void vq_mma_kernel(
    const float* __restrict__ Z, const float* __restrict__ E)
{
    extern __shared__ __align__(16) char sm[];
    float* Zs    = reinterpret_cast<float*>(sm + SM_Z);
    float* ESALL = reinterpret_cast<float*>(sm + SM_ESALL);
    float* ZSQ   = reinterpret_cast<float*>(sm + SM_ZSQ);
    float* RV    = reinterpret_cast<float*>(sm + SM_RV);
    int*   RI    = reinterpret_cast<int*>(sm + SM_RI);
    const uint32_t smb = smem_u32(sm);

    const int tid  = threadIdx.x;
    const int lane = tid & 31;
    const int warp = tid >> 5;
    const int cg   = warp & 1;          // col group (0/1) -> 64 cols
    const int rw   = warp >> 1;         // row group (0..3) -> 32 rows
    const int g    = lane >> 2;         // 0..7
    const int tq   = lane & 3;          // 0..3
    const int rowBase = blockIdx.x * BM;

    // ---- e_sq table: whole thing into smem via cp.async (once) ----
#pragma unroll
    for (int i = 0; i < 8; i++) {
        int c = tid + i * 256;          // 0..2047 float4 chunks
        cp16(smb + SM_ESALL + c * 16, g_esq + c * 4);
    }
    CP_COMMIT();

    // ---- prologue: stage B tiles 0 and 1 (LDG -> split -> STS) ----
    float4 pf[8];
    ldg_half(pf, E, tid);
    split_sts_half(pf, sm + SM_B0, tid);
    ldg_half(pf, E + (size_t)BN * DDIM, tid);
    split_sts_half(pf, sm + SM_B1, tid);

    // ---- stage Z tile (plain fp32, pad-68 rows) ----
    {
        const float4* zp = reinterpret_cast<const float4*>(Z + (size_t)rowBase * DDIM);
#pragma unroll
        for (int i = 0; i < 8; i++) {
            int c = tid + i * 256;
            int m = c >> 4, kc = c & 15;
            float4 v = zp[c];
            *reinterpret_cast<float4*>(&Zs[m * 68 + kc * 4]) = v;
        }
    }
    __syncthreads();

    // ---- zsq: exact sequential fp32 chain ----
    if (tid < BM) {
        float s = 0.f;
#pragma unroll
        for (int d = 0; d < DDIM; d++) {
            float v = Zs[tid * 68 + d];
            s = fmaf(v, v, s);
        }
        ZSQ[tid] = s;
    }

    // ---- build A fragments (bf16 hi + lo residual), registers ----
    uint32_t ah[2][4][4], al[2][4][4];
#pragma unroll
    for (int mf = 0; mf < 2; mf++) {
        const int r0 = rw * 32 + mf * 16 + g;
#pragma unroll
        for (int kc = 0; kc < 4; kc++) {
            const int k0 = kc * 16 + 2 * tq;
            float2 p0 = *reinterpret_cast<const float2*>(&Zs[r0 * 68 + k0]);
            float2 p1 = *reinterpret_cast<const float2*>(&Zs[(r0 + 8) * 68 + k0]);
            float2 p2 = *reinterpret_cast<const float2*>(&Zs[r0 * 68 + k0 + 8]);
            float2 p3 = *reinterpret_cast<const float2*>(&Zs[(r0 + 8) * 68 + k0 + 8]);
            split_pair(p0.x, p0.y, ah[mf][kc][0], al[mf][kc][0]);
            split_pair(p1.x, p1.y, ah[mf][kc][1], al[mf][kc][1]);
            split_pair(p2.x, p2.y, ah[mf][kc][2], al[mf][kc][2]);
            split_pair(p3.x, p3.y, ah[mf][kc][3], al[mf][kc][3]);
        }
    }
    CP_WAIT0();
    __syncthreads();    // ZSQ + B0/B1 + ESALL visible

    float zsqv[4];
#pragma unroll
    for (int ri = 0; ri < 4; ri++)
        zsqv[ri] = ZSQ[rw * 32 + (ri >> 1) * 16 + g + (ri & 1) * 8];

    float bv[4]; int bi[4];
#pragma unroll
    for (int ri = 0; ri < 4; ri++) { bv[ri] = 3.4e38f; bi[ri] = 0; }

    const int swg = g << 2;
    int buf = 0;                        // t % 3

    for (int t = 0; t < NTILES; t++) {
        // prefetch raw f32 for tile t+2 (consumed by STS at iter end)
        if (t + 2 < NTILES)
            ldg_half(pf, E + (size_t)(t + 2) * BN * DDIM, tid);

        const char* Bbuf = sm + buf * 32768;

        float acc[2][8][4];
#pragma unroll
        for (int mf = 0; mf < 2; mf++)
#pragma unroll
            for (int nf = 0; nf < 8; nf++)
#pragma unroll
                for (int j = 0; j < 4; j++) acc[mf][nf][j] = 0.f;

#pragma unroll
        for (int kc = 0; kc < 4; kc++) {
#pragma unroll
            for (int nf = 0; nf < 8; nf++) {
                const char* rowp = Bbuf + (cg * 64 + nf * 8 + g) * 256;
                const int ki0 = ((kc * 8 + tq) ^ swg) << 3;
                uint2 v0 = *reinterpret_cast<const uint2*>(rowp + ki0);
                uint2 v1 = *reinterpret_cast<const uint2*>(rowp + (ki0 ^ 32));
#pragma unroll
                for (int mf = 0; mf < 2; mf++) {
                    mma16(acc[mf][nf], ah[mf][kc], v0.x, v1.x);   // hh
                    mma16(acc[mf][nf], ah[mf][kc], v0.y, v1.y);   // hl
                    mma16(acc[mf][nf], al[mf][kc], v0.x, v1.x);   // lh
                }
            }
        }

        // ---- epilogue: d2 = fl(fl(zsq - 2 dot) + es), running min ----
        const float* EST = ESALL + t * 128;
        const int colT = t * BN + cg * 64;
#pragma unroll
        for (int nf = 0; nf < 8; nf++) {
            float2 ep2 = *reinterpret_cast<const float2*>(
                &EST[cg * 64 + nf * 8 + 2 * tq]);
#pragma unroll
            for (int mf = 0; mf < 2; mf++) {
#pragma unroll
                for (int j = 0; j < 4; j++) {
                    float es = (j & 1) ? ep2.y : ep2.x;
                    int ri = mf * 2 + (j >> 1);
                    float tt = fmaf(-2.0f, acc[mf][nf][j], zsqv[ri]);
                    float d2 = tt + es;
                    int col = colT + nf * 8 + 2 * tq + (j & 1);
                    if (d2 < bv[ri]) { bv[ri] = d2; bi[ri] = col; }
                }
            }
        }

        // ---- split + STS tile t+2 into the buffer freed at iter t-1 ----
        if (t + 2 < NTILES) {
            int nbuf = buf + 2; if (nbuf >= 3) nbuf -= 3;
            split_sts_half(pf, sm + nbuf * 32768, tid);
        }
        __syncthreads();
        buf = (buf == 2) ? 0 : buf + 1;
    }

    // ---- reduce across the 4 tq lanes sharing each row (tie -> lowest col) ----
#pragma unroll
    for (int ri = 0; ri < 4; ri++) {
        float v = bv[ri];
        int   x = bi[ri];
#pragma unroll
        for (int off = 1; off <= 2; off <<= 1) {
            float ov = __shfl_xor_sync(0xFFFFFFFFu, v, off);
            int   ox = __shfl_xor_sync(0xFFFFFFFFu, x, off);
            if (ov < v || (ov == v && ox < x)) { v = ov; x = ox; }
        }
        bv[ri] = v; bi[ri] = x;
    }
    if (tq == 0 && cg == 0) {
#pragma unroll
        for (int ri = 0; ri < 4; ri++) {
            int row = rw * 32 + (ri >> 1) * 16 + g + (ri & 1) * 8;
            RV[row] = bv[ri]; RI[row] = bi[ri];
        }
    }
    __syncthreads();
    if (tq == 0 && cg == 1) {
#pragma unroll
        for (int ri = 0; ri < 4; ri++) {
            int row = rw * 32 + (ri >> 1) * 16 + g + (ri & 1) * 8;
            float v0 = RV[row]; int i0 = RI[row];
            int win = (bv[ri] < v0 || (bv[ri] == v0 && bi[ri] < i0)) ? bi[ri] : i0;
            g_idx[rowBase + row] = win;
        }
    }
}

// ---------------------------------------------------------------------------
// Kernel 3: gather + partial loss + index-as-float
// ---------------------------------------------------------------------------
__global__ __launch_bounds__(256) void gather_loss_kernel(
    const float* __restrict__ Z, const float* __restrict__ E,
    float* __restrict__ out)
{
    __shared__ float red[256];
    const int tid  = threadIdx.x;
    const int gtid = blockIdx.x * blockDim.x + tid;

    float lsum = 0.f;
    const float4* Z4 = reinterpret_cast<const float4*>(Z);
    float4* O4 = reinterpret_cast<float4*>(out);

#pragma unroll
    for (int j = 0; j < 4; j++) {
        int f   = gtid * 4 + j;
        int row = f >> 4;
        int dc  = (f & 15);
        int idx = g_idx[row];
        const float4* E4 = reinterpret_cast<const float4*>(E + (size_t)idx * DDIM);
        float4 q = E4[dc];
        float4 z = Z4[f];
        O4[f] = q;
        float dx = z.x - q.x, dy = z.y - q.y, dz = z.z - q.z, dw = z.w - q.w;
        lsum += dx * dx + dy * dy + dz * dz + dw * dw;
    }

    if (gtid < NROWS) out[OUT_IDX + gtid] = (float)g_idx[gtid];

    red[tid] = lsum;
    __syncthreads();
    for (int s = 128; s > 0; s >>= 1) {
        if (tid < s) red[tid] += red[tid + s];
        __syncthreads();
    }
    if (tid == 0) g_partial[blockIdx.x] = red[0];
}

// ---------------------------------------------------------------------------
// Kernel 4: finalize losses
// ---------------------------------------------------------------------------
__global__ __launch_bounds__(512) void finalize_kernel(float* __restrict__ out) {
    __shared__ float red[512];
    int tid = threadIdx.x;
    red[tid] = g_partial[tid] + g_partial[tid + 512];
    __syncthreads();
    for (int s = 256; s > 0; s >>= 1) {
        if (tid < s) red[tid] += red[tid + s];
        __syncthreads();
    }
    if (tid == 0) {
        float loss = red[0] * (1.0f / (float)(NROWS * DDIM)); // N*D = 2^22, exact
        out[OUT_LOSS + 0] = loss;
        out[OUT_LOSS + 1] = loss;
    }
}

// ---------------------------------------------------------------------------
extern "C" void kernel_launch(void* const* d_in, const int* in_sizes, int n_in,
                              void* d_out, int out_size)
{
    const float* Z = (const float*)d_in[0];
    const float* E = (const float*)d_in[1];
    if (n_in >= 2 && in_sizes[0] == KEMB * DDIM && in_sizes[1] == NROWS * DDIM) {
        const float* t = Z; Z = E; E = t;
    }
    float* out = (float*)d_out;

    cudaFuncSetAttribute(vq_mma_kernel,
                         cudaFuncAttributeMaxDynamicSharedMemorySize, SMEM_TOTAL);

    esq_kernel<<<KEMB / 256, 256>>>(E);
    vq_mma_kernel<<<NROWS / BM, NTHREADS, SMEM_TOTAL>>>(Z, E);
    gather_loss_kernel<<<NPARTIAL, 256>>>(Z, E, out);
    finalize_kernel<<<1, 512>>>(out);
}

// round 10
// speedup vs baseline: 1.5148x; 1.4644x over previous
#include <cuda_runtime.h>
#include <cstdint>

// Problem constants
#define NROWS 65536
#define DDIM  64
#define KEMB  8192

#define BM 128
#define BN 128
#define NTILES (KEMB / BN)      // 64
#define NTHREADS 256            // 8 warps: 4 row-groups x 2 col-groups

// Output layout (flattened fp32): quantized | vq_loss | commit_loss | idx
#define OUT_LOSS   (NROWS * DDIM)
#define OUT_IDX    (NROWS * DDIM + 2)
#define NPARTIAL   1024

// smem byte offsets
#define SM_B0    0               // 32768: pre-split B tile ([n][kw] (hi,lo) pairs)
#define SM_B1    32768
#define SM_ESALL 65536           // 32768: all 8192 e_sq values
#define SM_Z     98304           // 34816: 128 x 68 f32 (padded)
#define SM_ZSQ   133120          // 512
#define SM_RV    133632          // 512
#define SM_RI    134144          // 512
#define SMEM_TOTAL 134656

typedef unsigned long long ull;

// scratch
__device__ float g_esq[KEMB];
__device__ ull   g_ehl[KEMB * 32];   // pre-split E: per row 32 (hi,lo) bf16x2 pairs, swizzled
__device__ int   g_idx[NROWS];
__device__ float g_partial[NPARTIAL];

// ---------------------------------------------------------------------------
__device__ __forceinline__ uint32_t pack_bf16x2(float lo, float hi) {
    uint32_t d;
    asm("cvt.rn.bf16x2.f32 %0, %1, %2;" : "=r"(d) : "f"(hi), "f"(lo));
    return d;
}
__device__ __forceinline__ float bf_lo(uint32_t u) { return __uint_as_float(u << 16); }
__device__ __forceinline__ float bf_hi(uint32_t u) { return __uint_as_float(u & 0xffff0000u); }

__device__ __forceinline__ void split_pair(float f0, float f1,
                                           uint32_t& h, uint32_t& l) {
    h = pack_bf16x2(f0, f1);
    l = pack_bf16x2(f0 - bf_lo(h), f1 - bf_hi(h));
}

__device__ __forceinline__ void mma16(float c[4], const uint32_t a[4],
                                      uint32_t b0, uint32_t b1) {
    asm volatile(
        "mma.sync.aligned.m16n8k16.row.col.f32.bf16.bf16.f32 "
        "{%0,%1,%2,%3},{%4,%5,%6,%7},{%8,%9},{%0,%1,%2,%3};"
        : "+f"(c[0]), "+f"(c[1]), "+f"(c[2]), "+f"(c[3])
        : "r"(a[0]), "r"(a[1]), "r"(a[2]), "r"(a[3]), "r"(b0), "r"(b1));
}
__device__ __forceinline__ uint32_t smem_u32(const void* p) {
    uint32_t a;
    asm("{ .reg .u64 t; cvta.to.shared.u64 t, %1; cvt.u32.u64 %0, t; }"
        : "=r"(a) : "l"(p));
    return a;
}
__device__ __forceinline__ void cp16(uint32_t dst, const void* src) {
    asm volatile("cp.async.cg.shared.global [%0], [%1], 16;"
                 :: "r"(dst), "l"(src) : "memory");
}
#define CP_COMMIT() asm volatile("cp.async.commit_group;" ::: "memory")
#define CP_WAIT1()  asm volatile("cp.async.wait_group 1;" ::: "memory")
#define CP_WAIT0()  asm volatile("cp.async.wait_group 0;" ::: "memory")

// ---------------------------------------------------------------------------
// Kernel 1a: e_sq (sequential fp32 chain)
// ---------------------------------------------------------------------------
__global__ void esq_kernel(const float* __restrict__ E) {
    int k = blockIdx.x * blockDim.x + threadIdx.x;
    if (k < KEMB) {
        const float* row = E + k * DDIM;
        float s = 0.f;
#pragma unroll
        for (int d = 0; d < DDIM; d++) s = fmaf(row[d], row[d], s);
        g_esq[k] = s;
    }
}

// ---------------------------------------------------------------------------
// Kernel 1b: pre-split E into interleaved (hi,lo) bf16x2 pairs, row-swizzled.
// Row n (256 B): pair kw stored at ull index (kw ^ ((n&7)<<2)).
// ---------------------------------------------------------------------------
__global__ void esplit_kernel(const float* __restrict__ E) {
    int n = blockIdx.x * blockDim.x + threadIdx.x;
    if (n < KEMB) {
        const float4* sp = reinterpret_cast<const float4*>(E + (size_t)n * DDIM);
        ull* row = g_ehl + (size_t)n * 32;
        const int sw = (n & 7) << 2;
#pragma unroll
        for (int q = 0; q < 16; q++) {
            float4 v = sp[q];
            uint32_t h0, l0, h1, l1;
            split_pair(v.x, v.y, h0, l0);
            split_pair(v.z, v.w, h1, l1);
            int kw = q * 2;
            row[kw ^ sw]       = (ull)h0 | ((ull)l0 << 32);
            row[(kw + 1) ^ sw] = (ull)h1 | ((ull)l1 << 32);
        }
    }
}

// ---------------------------------------------------------------------------
// Kernel 2: bf16 3-term split argmin GEMM, cp.async of pre-split B
// ---------------------------------------------------------------------------
__global__ __launch_bounds__(NTHREADS, 1) void vq_mma_kernel(
    const float* __restrict__ Z, const float* __restrict__ E)
{
    extern __shared__ __align__(16) char sm[];
    float* Zs    = reinterpret_cast<float*>(sm + SM_Z);
    float* ESALL = reinterpret_cast<float*>(sm + SM_ESALL);
    float* ZSQ   = reinterpret_cast<float*>(sm + SM_ZSQ);
    float* RV    = reinterpret_cast<float*>(sm + SM_RV);
    int*   RI    = reinterpret_cast<int*>(sm + SM_RI);
    const uint32_t smb = smem_u32(sm);

    const int tid  = threadIdx.x;
    const int lane = tid & 31;
    const int warp = tid >> 5;
    const int cg   = warp & 1;          // col group (0/1) -> 64 cols
    const int rw   = warp >> 1;         // row group (0..3) -> 32 rows
    const int g    = lane >> 2;         // 0..7
    const int tq   = lane & 3;          // 0..3
    const int rowBase = blockIdx.x * BM;

    const char* EHL = reinterpret_cast<const char*>(g_ehl);

    // ---- group 0: e_sq table (32 KB) + B tile 0 (32 KB verbatim copy) ----
#pragma unroll
    for (int i = 0; i < 8; i++) {
        int c = tid + i * 256;
        cp16(smb + SM_ESALL + c * 16, g_esq + c * 4);
    }
#pragma unroll
    for (int i = 0; i < 8; i++) {
        int c = tid + i * 256;          // 0..2047 16B chunks
        cp16(smb + SM_B0 + c * 16, EHL + c * 16);
    }
    CP_COMMIT();
    // ---- group 1: B tile 1 ----
#pragma unroll
    for (int i = 0; i < 8; i++) {
        int c = tid + i * 256;
        cp16(smb + SM_B1 + c * 16, EHL + 32768 + c * 16);
    }
    CP_COMMIT();

    // ---- stage Z tile (plain fp32, pad-68 rows) ----
    {
        const float4* zp = reinterpret_cast<const float4*>(Z + (size_t)rowBase * DDIM);
#pragma unroll
        for (int i = 0; i < 8; i++) {
            int c = tid + i * 256;
            int m = c >> 4, kc = c & 15;
            float4 v = zp[c];
            *reinterpret_cast<float4*>(&Zs[m * 68 + kc * 4]) = v;
        }
    }
    __syncthreads();

    // ---- zsq: exact sequential fp32 chain ----
    if (tid < BM) {
        float s = 0.f;
#pragma unroll
        for (int d = 0; d < DDIM; d++) {
            float v = Zs[tid * 68 + d];
            s = fmaf(v, v, s);
        }
        ZSQ[tid] = s;
    }

    // ---- build A fragments (bf16 hi + lo residual), registers ----
    uint32_t ah[2][4][4], al[2][4][4];
#pragma unroll
    for (int mf = 0; mf < 2; mf++) {
        const int r0 = rw * 32 + mf * 16 + g;
#pragma unroll
        for (int kc = 0; kc < 4; kc++) {
            const int k0 = kc * 16 + 2 * tq;
            float2 p0 = *reinterpret_cast<const float2*>(&Zs[r0 * 68 + k0]);
            float2 p1 = *reinterpret_cast<const float2*>(&Zs[(r0 + 8) * 68 + k0]);
            float2 p2 = *reinterpret_cast<const float2*>(&Zs[r0 * 68 + k0 + 8]);
            float2 p3 = *reinterpret_cast<const float2*>(&Zs[(r0 + 8) * 68 + k0 + 8]);
            split_pair(p0.x, p0.y, ah[mf][kc][0], al[mf][kc][0]);
            split_pair(p1.x, p1.y, ah[mf][kc][1], al[mf][kc][1]);
            split_pair(p2.x, p2.y, ah[mf][kc][2], al[mf][kc][2]);
            split_pair(p3.x, p3.y, ah[mf][kc][3], al[mf][kc][3]);
        }
    }

    float zsqv[4];
    float bv[4]; int bi[4];

    CP_WAIT1();          // group 0 (ESALL + B0) done
    __syncthreads();

#pragma unroll
    for (int ri = 0; ri < 4; ri++) {
        zsqv[ri] = ZSQ[rw * 32 + (ri >> 1) * 16 + g + (ri & 1) * 8];
        bv[ri] = 3.4e38f; bi[ri] = 0;
    }

    const int swg = g << 2;

    for (int t = 0; t < NTILES; t++) {
        if (t) {
            if (t >= NTILES - 1) { CP_WAIT0(); } else { CP_WAIT1(); }
            __syncthreads();
        }

        const char* Bbuf = sm + ((t & 1) ? SM_B1 : SM_B0);

        float acc[2][8][4];
#pragma unroll
        for (int mf = 0; mf < 2; mf++)
#pragma unroll
            for (int nf = 0; nf < 8; nf++)
#pragma unroll
                for (int j = 0; j < 4; j++) acc[mf][nf][j] = 0.f;

#pragma unroll
        for (int kc = 0; kc < 4; kc++) {
#pragma unroll
            for (int nf = 0; nf < 8; nf++) {
                const char* rowp = Bbuf + (cg * 64 + nf * 8 + g) * 256;
                const int ki0 = ((kc * 8 + tq) ^ swg) << 3;
                uint2 v0 = *reinterpret_cast<const uint2*>(rowp + ki0);
                uint2 v1 = *reinterpret_cast<const uint2*>(rowp + (ki0 ^ 32));
#pragma unroll
                for (int mf = 0; mf < 2; mf++) {
                    mma16(acc[mf][nf], ah[mf][kc], v0.x, v1.x);   // hh
                    mma16(acc[mf][nf], ah[mf][kc], v0.y, v1.y);   // hl
                    mma16(acc[mf][nf], al[mf][kc], v0.x, v1.x);   // lh
                }
            }
        }

        // ---- epilogue: d2 = fl(fl(zsq - 2 dot) + es), running min ----
        const float* EST = ESALL + t * 128;
        const int colT = t * BN + cg * 64;
#pragma unroll
        for (int nf = 0; nf < 8; nf++) {
            float2 ep2 = *reinterpret_cast<const float2*>(
                &EST[cg * 64 + nf * 8 + 2 * tq]);
#pragma unroll
            for (int mf = 0; mf < 2; mf++) {
#pragma unroll
                for (int j = 0; j < 4; j++) {
                    float es = (j & 1) ? ep2.y : ep2.x;
                    int ri = mf * 2 + (j >> 1);
                    float tt = fmaf(-2.0f, acc[mf][nf][j], zsqv[ri]);
                    float d2 = tt + es;
                    int col = colT + nf * 8 + 2 * tq + (j & 1);
                    if (d2 < bv[ri]) { bv[ri] = d2; bi[ri] = col; }
                }
            }
        }

        __syncthreads();

        // ---- issue cp.async for tile t+2 into the buffer just freed ----
        if (t + 2 < NTILES) {
            const uint32_t dbase = smb + ((t & 1) ? SM_B1 : SM_B0);
            const char* src = EHL + (size_t)(t + 2) * 32768;
#pragma unroll
            for (int i = 0; i < 8; i++) {
                int c = tid + i * 256;
                cp16(dbase + c * 16, src + c * 16);
            }
            CP_COMMIT();
        }
    }

    // ---- reduce across the 4 tq lanes sharing each row (tie -> lowest col) ----
#pragma unroll
    for (int ri = 0; ri < 4; ri++) {
        float v = bv[ri];
        int   x = bi[ri];
#pragma unroll
        for (int off = 1; off <= 2; off <<= 1) {
            float ov = __shfl_xor_sync(0xFFFFFFFFu, v, off);
            int   ox = __shfl_xor_sync(0xFFFFFFFFu, x, off);
            if (ov < v || (ov == v && ox < x)) { v = ov; x = ox; }
        }
        bv[ri] = v; bi[ri] = x;
    }
    if (tq == 0 && cg == 0) {
#pragma unroll
        for (int ri = 0; ri < 4; ri++) {
            int row = rw * 32 + (ri >> 1) * 16 + g + (ri & 1) * 8;
            RV[row] = bv[ri]; RI[row] = bi[ri];
        }
    }
    __syncthreads();
    if (tq == 0 && cg == 1) {
#pragma unroll
        for (int ri = 0; ri < 4; ri++) {
            int row = rw * 32 + (ri >> 1) * 16 + g + (ri & 1) * 8;
            float v0 = RV[row]; int i0 = RI[row];
            int win = (bv[ri] < v0 || (bv[ri] == v0 && bi[ri] < i0)) ? bi[ri] : i0;
            g_idx[rowBase + row] = win;
        }
    }
}

// ---------------------------------------------------------------------------
// Kernel 3: gather + partial loss + index-as-float
// ---------------------------------------------------------------------------
__global__ __launch_bounds__(256) void gather_loss_kernel(
    const float* __restrict__ Z, const float* __restrict__ E,
    float* __restrict__ out)
{
    __shared__ float red[256];
    const int tid  = threadIdx.x;
    const int gtid = blockIdx.x * blockDim.x + tid;

    float lsum = 0.f;
    const float4* Z4 = reinterpret_cast<const float4*>(Z);
    float4* O4 = reinterpret_cast<float4*>(out);

#pragma unroll
    for (int j = 0; j < 4; j++) {
        int f   = gtid * 4 + j;
        int row = f >> 4;
        int dc  = (f & 15);
        int idx = g_idx[row];
        const float4* E4 = reinterpret_cast<const float4*>(E + (size_t)idx * DDIM);
        float4 q = E4[dc];
        float4 z = Z4[f];
        O4[f] = q;
        float dx = z.x - q.x, dy = z.y - q.y, dz = z.z - q.z, dw = z.w - q.w;
        lsum += dx * dx + dy * dy + dz * dz + dw * dw;
    }

    if (gtid < NROWS) out[OUT_IDX + gtid] = (float)g_idx[gtid];

    red[tid] = lsum;
    __syncthreads();
    for (int s = 128; s > 0; s >>= 1) {
        if (tid < s) red[tid] += red[tid + s];
        __syncthreads();
    }
    if (tid == 0) g_partial[blockIdx.x] = red[0];
}

// ---------------------------------------------------------------------------
// Kernel 4: finalize losses
// ---------------------------------------------------------------------------
__global__ __launch_bounds__(512) void finalize_kernel(float* __restrict__ out) {
    __shared__ float red[512];
    int tid = threadIdx.x;
    red[tid] = g_partial[tid] + g_partial[tid + 512];
    __syncthreads();
    for (int s = 256; s > 0; s >>= 1) {
        if (tid < s) red[tid] += red[tid + s];
        __syncthreads();
    }
    if (tid == 0) {
        float loss = red[0] * (1.0f / (float)(NROWS * DDIM)); // N*D = 2^22, exact
        out[OUT_LOSS + 0] = loss;
        out[OUT_LOSS + 1] = loss;
    }
}

// ---------------------------------------------------------------------------
extern "C" void kernel_launch(void* const* d_in, const int* in_sizes, int n_in,
                              void* d_out, int out_size)
{
    const float* Z = (const float*)d_in[0];
    const float* E = (const float*)d_in[1];
    if (n_in >= 2 && in_sizes[0] == KEMB * DDIM && in_sizes[1] == NROWS * DDIM) {
        const float* t = Z; Z = E; E = t;
    }
    float* out = (float*)d_out;

    cudaFuncSetAttribute(vq_mma_kernel,
                         cudaFuncAttributeMaxDynamicSharedMemorySize, SMEM_TOTAL);

    esq_kernel<<<KEMB / 256, 256>>>(E);
    esplit_kernel<<<KEMB / 256, 256>>>(E);
    vq_mma_kernel<<<NROWS / BM, NTHREADS, SMEM_TOTAL>>>(Z, E);
    gather_loss_kernel<<<NPARTIAL, 256>>>(Z, E, out);
    finalize_kernel<<<1, 512>>>(out);
}